// round 10
// baseline (speedup 1.0000x reference)
#include <cuda_runtime.h>
#include <cuda_fp16.h>
#include <cstdint>

#define TOTAL_LEN 0.078f
#define NGRID 129
#define NIN 72
#define NY 17
#define BROWS 65536
#define NOUT 1224        // 72*17
#define NMIROUT 969      // 57*17
#define OUT_STRIDE 2193  // 129*17
#define KDIM 100

// Table: 256 intervals over [-8, 8]
#define NT_INT 256
#define XMIN (-8.0f)
#define XMAX 8.0f
#define XSCALE 16.0f     // 256/16
#define TROWS 320        // table rows computed (257 used), 5*64 for gemm tiling
#define TEXT 2196        // extended row stride (2193 padded to mult of 4)

// Device scratch (no allocations allowed)
__device__ __align__(16) float   g_table[TROWS * NOUT];       // xg table fp32, ~1.6 MB
// Per interval i, per column c: half2{ v0, v1-v0 }. 4 column-shifted replicas.
__device__ __align__(16) __half2 g_ext[4 * NT_INT * TEXT];    // ~9 MB, L2-resident

__device__ __forceinline__ float sigmoid_fast(float z) {
    return 1.0f / (1.0f + __expf(-z));
}

// ---------------------------------------------------------------------------
// K1: table = sigmoid(H2(p) @ W3 + b3), with layers 1+2 computed inline.
// Grid (TROWS/64, 1224/72), 256 threads. Block tile 64x72.
// ---------------------------------------------------------------------------
#define TB_KC 50
__global__ void __launch_bounds__(256) table_gemm_kernel(const float* __restrict__ W1,
                                                         const float* __restrict__ b1,
                                                         const float* __restrict__ W2,
                                                         const float* __restrict__ b2,
                                                         const float* __restrict__ W3,
                                                         const float* __restrict__ b3) {
    __shared__ float As[64][101];
    __shared__ float Bs[TB_KC][72];
    __shared__ float sW1[10], sb1[10], sW2[1000], sb2[100];

    int tid = threadIdx.x;
    int tm = tid & 31;
    int tn = tid >> 5;
    int p0 = blockIdx.x * 64;
    int n0 = blockIdx.y * 72;

    if (tid < 10) { sW1[tid] = W1[tid]; sb1[tid] = b1[tid]; }
    if (tid >= 32 && tid < 132) sb2[tid - 32] = b2[tid - 32];
    for (int i = tid; i < 1000; i += 256) sW2[i] = W2[i];
    __syncthreads();

    // Inline layers 1+2: 256 threads = 64 rows x 4 col-groups of 25
    {
        int r = tid & 63;          // row within tile
        int cg = tid >> 6;         // col group 0..3
        float xv = XMIN + (float)(p0 + r) * (1.0f / XSCALE);
        float h1[10];
#pragma unroll
        for (int j = 0; j < 10; j++)
            h1[j] = sigmoid_fast(fmaf(xv, sW1[j], sb1[j]));
#pragma unroll 5
        for (int c = cg * 25; c < cg * 25 + 25; c++) {
            float s = sb2[c];
#pragma unroll
            for (int j = 0; j < 10; j++) s = fmaf(h1[j], sW2[j * 100 + c], s);
            As[r][c] = sigmoid_fast(s);
        }
    }

    float acc[2][9];
#pragma unroll
    for (int a = 0; a < 2; a++)
#pragma unroll
        for (int j = 0; j < 9; j++) acc[a][j] = 0.0f;

    for (int ch = 0; ch < 2; ch++) {
        int kb = ch * TB_KC;
        __syncthreads();
        for (int idx = tid; idx < TB_KC * 72; idx += 256) {
            int k = idx / 72, n = idx - k * 72;
            Bs[k][n] = W3[(kb + k) * NOUT + n0 + n];
        }
        __syncthreads();
#pragma unroll 5
        for (int k = 0; k < TB_KC; k++) {
            float a0 = As[tm][kb + k];
            float a1 = As[tm + 32][kb + k];
#pragma unroll
            for (int j = 0; j < 9; j++) {
                float bv = Bs[k][tn * 9 + j];
                acc[0][j] = fmaf(a0, bv, acc[0][j]);
                acc[1][j] = fmaf(a1, bv, acc[1][j]);
            }
        }
    }

#pragma unroll
    for (int j = 0; j < 9; j++) {
        int col = n0 + tn * 9 + j;
        float bias = __ldg(&b3[col]);
        g_table[(p0 + tm) * NOUT + col]      = sigmoid_fast(acc[0][j] + bias);
        g_table[(p0 + tm + 32) * NOUT + col] = sigmoid_fast(acc[1][j] + bias);
    }
}

// ---------------------------------------------------------------------------
// K2: per interval i (256 blocks): compute mirror params from xs in smem,
// extend rows i, i+1 to 2193 cols, pack half2{v0, v1-v0}, write 4 shifted
// replicas.
// ---------------------------------------------------------------------------
__global__ void __launch_bounds__(256) extend_kernel(const float* __restrict__ xs) {
    __shared__ float x0[NOUT], x1[NOUT];
    __shared__ float sxs[NGRID];
    __shared__ int2  spack[NMIROUT];

    int p = blockIdx.x;          // interval 0..255
    int tid = threadIdx.x;

    for (int i = tid; i < NGRID; i += 256) sxs[i] = xs[i];
    const float* r0 = g_table + (size_t)p * NOUT;
    for (int c = tid; c < NOUT; c += 256) {
        x0[c] = r0[c];
        x1[c] = r0[c + NOUT];    // row p+1
    }
    __syncthreads();

    // mirror params (969), computed locally
    for (int m = tid; m < NMIROUT; m += 256) {
        int jj = m / NY;
        int y  = m - jj * NY;
        float x_pos = TOTAL_LEN - sxs[NIN + jj];
        bool near = (TOTAL_LEN - x_pos) < 0.02f;
        int s1, s2; float w;
        if (near) {
            int best = 0; float bd = fabsf(x_pos - sxs[0]);
            for (int i = 1; i < NGRID; i++) {
                float d = fabsf(x_pos - sxs[i]);
                if (d < bd) { bd = d; best = i; }
            }
            if (best > NIN - 1) best = NIN - 1;
            s1 = best * NY + y; s2 = s1; w = 1.0f;
        } else {
            int cnt = 0;
            for (int i = 0; i < NGRID; i++) cnt += (sxs[i] <= x_pos) ? 1 : 0;
            int c1 = cnt - 1;
            if (c1 < 0) c1 = 0;
            if (c1 > NIN - 2) c1 = NIN - 2;
            s1 = c1 * NY + y; s2 = (c1 + 1) * NY + y;
            w = (sxs[c1 + 1] - x_pos) / (sxs[c1 + 1] - sxs[c1]);
        }
        spack[m] = make_int2(s1 | (s2 << 16), __float_as_int(w));
    }
    __syncthreads();

    for (int c = tid; c < OUT_STRIDE; c += 256) {
        float v0, v1;
        if (c < NOUT) {
            v0 = x0[c];
            v1 = x1[c];
        } else {
            int2 pk = spack[c - NOUT];
            int s1 = pk.x & 0xFFFF;
            int s2 = pk.x >> 16;
            float w = __int_as_float(pk.y);
            v0 = fmaf(w, x0[s1] - x0[s2], x0[s2]);
            v1 = fmaf(w, x1[s1] - x1[s2], x1[s2]);
        }
        __half2 h = __floats2half2_rn(v0, v1 - v0);
#pragma unroll
        for (int r = 0; r < 4; r++) {
            int cc = c - r;
            if (cc >= 0)
                g_ext[(r * NT_INT + p) * TEXT + cc] = h;
        }
    }
}

// ---------------------------------------------------------------------------
// K3: eval. One block (192 thr) per sample. Single load stream:
// 16B LDG (4 cols of half2{v0,d}) -> cvt -> fp32 FMA -> 16B evict-first STG.
// ---------------------------------------------------------------------------
__global__ void __launch_bounds__(192) eval_kernel(const float* __restrict__ x,
                                                   float* __restrict__ out) {
    int b = blockIdx.x;
    int tid = threadIdx.x;

    float xv = fminf(fmaxf(x[b], XMIN), XMAX);
    float u = (xv - XMIN) * XSCALE;
    int i = (int)u;
    if (i > NT_INT - 1) i = NT_INT - 1;
    float f = u - (float)i;

    int lead = (4 - (b & 3)) & 3;
    const __half2* rep  = g_ext + (lead * NT_INT + i) * TEXT;  // shifted replica
    const __half2* rep0 = g_ext + i * TEXT;                    // replica 0
    float* orow = out + (unsigned)b * OUT_STRIDE;

    // head (c < lead, at most 3): scalar from replica 0
    if (tid < lead) {
        float2 vd = __half22float2(__ldg(rep0 + tid));
        orow[tid] = fmaf(f, vd.y, vd.x);
    }

    // body: one aligned 16B load (4 columns) -> 4 FMA -> aligned 16B store
    int nv = (OUT_STRIDE - lead) >> 2;
    const uint4* a = (const uint4*)rep;
    float* obody = orow + lead;
#pragma unroll 3
    for (int v = tid; v < nv; v += 192) {
        uint4 r4 = __ldg(a + v);
        float2 c0 = __half22float2(*(const __half2*)&r4.x);
        float2 c1 = __half22float2(*(const __half2*)&r4.y);
        float2 c2 = __half22float2(*(const __half2*)&r4.z);
        float2 c3 = __half22float2(*(const __half2*)&r4.w);
        float4 o;
        o.x = fmaf(f, c0.y, c0.x);
        o.y = fmaf(f, c1.y, c1.x);
        o.z = fmaf(f, c2.y, c2.x);
        o.w = fmaf(f, c3.y, c3.x);
        __stcs((float4*)obody + v, o);
    }

    // tail (at most 3): scalar from replica 0
    for (int c = lead + 4 * nv + tid; c < OUT_STRIDE; c += 192) {
        float2 vd = __half22float2(__ldg(rep0 + c));
        orow[c] = fmaf(f, vd.y, vd.x);
    }
}

// ---------------------------------------------------------------------------
extern "C" void kernel_launch(void* const* d_in, const int* in_sizes, int n_in,
                              void* d_out, int out_size) {
    const float* x  = (const float*)d_in[0];
    const float* W1 = (const float*)d_in[1];
    const float* b1 = (const float*)d_in[2];
    const float* W2 = (const float*)d_in[3];
    const float* b2 = (const float*)d_in[4];
    const float* W3 = (const float*)d_in[5];
    const float* b3 = (const float*)d_in[6];
    const float* xs = (const float*)d_in[7];
    float* out = (float*)d_out;

    table_gemm_kernel<<<dim3(TROWS / 64, NOUT / 72), 256>>>(W1, b1, W2, b2, W3, b3);
    extend_kernel<<<NT_INT, 256>>>(xs);
    eval_kernel<<<BROWS, 192>>>(x, out);
}

// round 11
// speedup vs baseline: 1.6843x; 1.6843x over previous
#include <cuda_runtime.h>
#include <cuda_fp16.h>
#include <cstdint>

#define TOTAL_LEN 0.078f
#define NGRID 129
#define NIN 72
#define NY 17
#define BROWS 65536
#define NOUT 1224        // 72*17
#define NMIROUT 969      // 57*17
#define OUT_STRIDE 2193  // 129*17
#define KDIM 100

// Table: 256 intervals over [-8, 8]
#define NT_INT 256
#define XMIN (-8.0f)
#define XMAX 8.0f
#define XSCALE 16.0f     // 256/16
#define TROWS 320        // table rows computed (257 used), 5*64 for gemm tiling
#define TEXT 2196        // extended row stride (2193 padded to mult of 4)

// Device scratch (no allocations allowed)
__device__ __align__(16) float   g_tabH2[TROWS * KDIM];
__device__ __align__(16) float   g_table[TROWS * NOUT];       // xg table fp32, ~1.6 MB
// Per interval i, per column c: half2{ v0, v1-v0 }. 4 column-shifted replicas.
__device__ __align__(16) __half2 g_ext[4 * NT_INT * TEXT];    // ~9 MB, L2-resident
__device__ __align__(16) int2    g_pack[NMIROUT];             // {s1 | s2<<16, bits(w)}

__device__ __forceinline__ float sigmoid_fast(float z) {
    return 1.0f / (1.0f + __expf(-z));
}

// ---------------------------------------------------------------------------
// K1: blocks 0..319 -> layers 1+2 at grid point p
//     blocks 320..323 -> mirror interpolation params (969 packed entries)
// ---------------------------------------------------------------------------
__global__ void __launch_bounds__(256) setup_kernel(const float* __restrict__ W1,
                                                    const float* __restrict__ b1,
                                                    const float* __restrict__ W2,
                                                    const float* __restrict__ b2,
                                                    const float* __restrict__ xs) {
    int t = threadIdx.x;
    if (blockIdx.x < TROWS) {
        __shared__ float h1[10];
        int p = blockIdx.x;
        float xv = XMIN + (float)p * (1.0f / XSCALE);
        if (t < 10)
            h1[t] = sigmoid_fast(fmaf(xv, W1[t], b1[t]));
        __syncthreads();
        if (t < 100) {
            float s = b2[t];
#pragma unroll
            for (int j = 0; j < 10; j++) s = fmaf(h1[j], W2[j * 100 + t], s);
            g_tabH2[p * KDIM + t] = sigmoid_fast(s);
        }
    } else {
        __shared__ float sxs[NGRID];
        for (int i = t; i < NGRID; i += 256) sxs[i] = xs[i];
        __syncthreads();
        int m = (blockIdx.x - TROWS) * 256 + t;
        if (m >= NMIROUT) return;
        int jj = m / NY;
        int y  = m - jj * NY;
        float x_pos = TOTAL_LEN - sxs[NIN + jj];
        bool near = (TOTAL_LEN - x_pos) < 0.02f;
        int s1, s2; float w;
        if (near) {
            int best = 0; float bd = fabsf(x_pos - sxs[0]);
            for (int i = 1; i < NGRID; i++) {
                float d = fabsf(x_pos - sxs[i]);
                if (d < bd) { bd = d; best = i; }
            }
            if (best > NIN - 1) best = NIN - 1;
            s1 = best * NY + y; s2 = s1; w = 1.0f;
        } else {
            int cnt = 0;
            for (int i = 0; i < NGRID; i++) cnt += (sxs[i] <= x_pos) ? 1 : 0;
            int c1 = cnt - 1;
            if (c1 < 0) c1 = 0;
            if (c1 > NIN - 2) c1 = NIN - 2;
            s1 = c1 * NY + y; s2 = (c1 + 1) * NY + y;
            w = (sxs[c1 + 1] - x_pos) / (sxs[c1 + 1] - sxs[c1]);
        }
        g_pack[m] = make_int2(s1 | (s2 << 16), __float_as_int(w));
    }
}

// ---------------------------------------------------------------------------
// K2: table = sigmoid(H2grid @ W3 + b3)   [320 x 100] @ [100 x 1224]
// ---------------------------------------------------------------------------
#define TB_KC 50
__global__ void __launch_bounds__(256) table_gemm_kernel(const float* __restrict__ W3,
                                                         const float* __restrict__ b3) {
    __shared__ float As[64][101];
    __shared__ float Bs[TB_KC][72];

    int tid = threadIdx.x;
    int tm = tid & 31;
    int tn = tid >> 5;
    int p0 = blockIdx.x * 64;
    int n0 = blockIdx.y * 72;

    for (int idx = tid; idx < 64 * 100; idx += 256) {
        int r = idx / 100, k = idx - r * 100;
        As[r][k] = g_tabH2[(p0 + r) * KDIM + k];
    }

    float acc[2][9];
#pragma unroll
    for (int a = 0; a < 2; a++)
#pragma unroll
        for (int j = 0; j < 9; j++) acc[a][j] = 0.0f;

    for (int ch = 0; ch < 2; ch++) {
        int kb = ch * TB_KC;
        __syncthreads();
        for (int idx = tid; idx < TB_KC * 72; idx += 256) {
            int k = idx / 72, n = idx - k * 72;
            Bs[k][n] = W3[(kb + k) * NOUT + n0 + n];
        }
        __syncthreads();
#pragma unroll 5
        for (int k = 0; k < TB_KC; k++) {
            float a0 = As[tm][kb + k];
            float a1 = As[tm + 32][kb + k];
#pragma unroll
            for (int j = 0; j < 9; j++) {
                float bv = Bs[k][tn * 9 + j];
                acc[0][j] = fmaf(a0, bv, acc[0][j]);
                acc[1][j] = fmaf(a1, bv, acc[1][j]);
            }
        }
    }

#pragma unroll
    for (int j = 0; j < 9; j++) {
        int col = n0 + tn * 9 + j;
        float bias = __ldg(&b3[col]);
        g_table[(p0 + tm) * NOUT + col]      = sigmoid_fast(acc[0][j] + bias);
        g_table[(p0 + tm + 32) * NOUT + col] = sigmoid_fast(acc[1][j] + bias);
    }
}

// ---------------------------------------------------------------------------
// K3: per interval i (256 blocks): extend rows i and i+1 to 2193 cols via
// the mirror map, pack half2{v0, v1-v0}, write 4 column-shifted replicas.
// ---------------------------------------------------------------------------
__global__ void __launch_bounds__(256) extend_kernel() {
    __shared__ float x0[NOUT], x1[NOUT];
    int p = blockIdx.x;          // interval 0..255
    int tid = threadIdx.x;
    const float* r0 = g_table + (size_t)p * NOUT;
    for (int c = tid; c < NOUT; c += 256) {
        x0[c] = r0[c];
        x1[c] = r0[c + NOUT];    // row p+1
    }
    __syncthreads();

    for (int c = tid; c < OUT_STRIDE; c += 256) {
        float v0, v1;
        if (c < NOUT) {
            v0 = x0[c];
            v1 = x1[c];
        } else {
            int2 pk = g_pack[c - NOUT];
            int s1 = pk.x & 0xFFFF;
            int s2 = pk.x >> 16;
            float w = __int_as_float(pk.y);
            v0 = fmaf(w, x0[s1] - x0[s2], x0[s2]);
            v1 = fmaf(w, x1[s1] - x1[s2], x1[s2]);
        }
        __half2 h = __floats2half2_rn(v0, v1 - v0);
#pragma unroll
        for (int r = 0; r < 4; r++) {
            int cc = c - r;
            if (cc >= 0)
                g_ext[(r * NT_INT + p) * TEXT + cc] = h;
        }
    }
}

// ---------------------------------------------------------------------------
// K4: eval. One block (192 thr) per sample. Single load stream:
// 16B LDG (4 cols of half2{v0,d}) -> cvt -> fp32 FMA -> 16B evict-first STG.
// ---------------------------------------------------------------------------
__global__ void __launch_bounds__(192) eval_kernel(const float* __restrict__ x,
                                                   float* __restrict__ out) {
    int b = blockIdx.x;
    int tid = threadIdx.x;

    float xv = fminf(fmaxf(x[b], XMIN), XMAX);
    float u = (xv - XMIN) * XSCALE;
    int i = (int)u;
    if (i > NT_INT - 1) i = NT_INT - 1;
    float f = u - (float)i;

    int lead = (4 - (b & 3)) & 3;
    const __half2* rep  = g_ext + (lead * NT_INT + i) * TEXT;  // shifted replica
    const __half2* rep0 = g_ext + i * TEXT;                    // replica 0
    float* orow = out + (unsigned)b * OUT_STRIDE;

    // head (c < lead, at most 3): scalar from replica 0
    if (tid < lead) {
        float2 vd = __half22float2(__ldg(rep0 + tid));
        orow[tid] = fmaf(f, vd.y, vd.x);
    }

    // body: one aligned 16B load (4 columns) -> 4 FMA -> aligned 16B store
    int nv = (OUT_STRIDE - lead) >> 2;
    const uint4* a = (const uint4*)rep;
    float* obody = orow + lead;
#pragma unroll 3
    for (int v = tid; v < nv; v += 192) {
        uint4 r4 = __ldg(a + v);
        float2 c0 = __half22float2(*(const __half2*)&r4.x);
        float2 c1 = __half22float2(*(const __half2*)&r4.y);
        float2 c2 = __half22float2(*(const __half2*)&r4.z);
        float2 c3 = __half22float2(*(const __half2*)&r4.w);
        float4 o;
        o.x = fmaf(f, c0.y, c0.x);
        o.y = fmaf(f, c1.y, c1.x);
        o.z = fmaf(f, c2.y, c2.x);
        o.w = fmaf(f, c3.y, c3.x);
        __stcs((float4*)obody + v, o);
    }

    // tail (at most 3): scalar from replica 0
    for (int c = lead + 4 * nv + tid; c < OUT_STRIDE; c += 192) {
        float2 vd = __half22float2(__ldg(rep0 + c));
        orow[c] = fmaf(f, vd.y, vd.x);
    }
}

// ---------------------------------------------------------------------------
extern "C" void kernel_launch(void* const* d_in, const int* in_sizes, int n_in,
                              void* d_out, int out_size) {
    const float* x  = (const float*)d_in[0];
    const float* W1 = (const float*)d_in[1];
    const float* b1 = (const float*)d_in[2];
    const float* W2 = (const float*)d_in[3];
    const float* b2 = (const float*)d_in[4];
    const float* W3 = (const float*)d_in[5];
    const float* b3 = (const float*)d_in[6];
    const float* xs = (const float*)d_in[7];
    float* out = (float*)d_out;

    setup_kernel<<<TROWS + 4, 256>>>(W1, b1, W2, b2, xs);
    table_gemm_kernel<<<dim3(TROWS / 64, NOUT / 72), 256>>>(W3, b3);
    extend_kernel<<<NT_INT, 256>>>();
    eval_kernel<<<BROWS, 192>>>(x, out);
}

// round 12
// speedup vs baseline: 1.7191x; 1.0207x over previous
#include <cuda_runtime.h>
#include <cuda_fp16.h>
#include <cstdint>

#define TOTAL_LEN 0.078f
#define NGRID 129
#define NIN 72
#define NY 17
#define BROWS 65536
#define NOUT 1224        // 72*17
#define NMIROUT 969      // 57*17
#define OUT_STRIDE 2193  // 129*17
#define KDIM 100

// Table: 128 intervals over [-8, 8]
#define NT_INT 128
#define XMIN (-8.0f)
#define XMAX 8.0f
#define XSCALE 8.0f      // 128/16
#define TROWS 192        // table rows computed (129 used), 3*64 for gemm tiling
#define TEXT 2196        // extended row stride (2193 padded to mult of 4)

// Device scratch (no allocations allowed)
__device__ __align__(16) float   g_tabH2[TROWS * KDIM];
__device__ __align__(16) float   g_table[TROWS * NOUT];       // xg table fp32, ~0.94 MB
// Per interval i, per column c: half2{ v0, v1-v0 }. 4 column-shifted replicas.
__device__ __align__(16) __half2 g_ext[4 * NT_INT * TEXT];    // ~4.5 MB, L2-resident
__device__ __align__(16) int2    g_pack[NMIROUT];             // {s1 | s2<<16, bits(w)}

__device__ __forceinline__ float sigmoid_fast(float z) {
    return 1.0f / (1.0f + __expf(-z));
}

// ---------------------------------------------------------------------------
// K1: blocks 0..191 -> layers 1+2 at grid point p
//     blocks 192..195 -> mirror interpolation params (969 packed entries)
// ---------------------------------------------------------------------------
__global__ void __launch_bounds__(256) setup_kernel(const float* __restrict__ W1,
                                                    const float* __restrict__ b1,
                                                    const float* __restrict__ W2,
                                                    const float* __restrict__ b2,
                                                    const float* __restrict__ xs) {
    int t = threadIdx.x;
    if (blockIdx.x < TROWS) {
        __shared__ float h1[10];
        int p = blockIdx.x;
        float xv = XMIN + (float)p * (1.0f / XSCALE);
        if (t < 10)
            h1[t] = sigmoid_fast(fmaf(xv, W1[t], b1[t]));
        __syncthreads();
        if (t < 100) {
            float s = b2[t];
#pragma unroll
            for (int j = 0; j < 10; j++) s = fmaf(h1[j], W2[j * 100 + t], s);
            g_tabH2[p * KDIM + t] = sigmoid_fast(s);
        }
    } else {
        __shared__ float sxs[NGRID];
        for (int i = t; i < NGRID; i += 256) sxs[i] = xs[i];
        __syncthreads();
        int m = (blockIdx.x - TROWS) * 256 + t;
        if (m >= NMIROUT) return;
        int jj = m / NY;
        int y  = m - jj * NY;
        float x_pos = TOTAL_LEN - sxs[NIN + jj];
        bool near = (TOTAL_LEN - x_pos) < 0.02f;
        int s1, s2; float w;
        if (near) {
            int best = 0; float bd = fabsf(x_pos - sxs[0]);
            for (int i = 1; i < NGRID; i++) {
                float d = fabsf(x_pos - sxs[i]);
                if (d < bd) { bd = d; best = i; }
            }
            if (best > NIN - 1) best = NIN - 1;
            s1 = best * NY + y; s2 = s1; w = 1.0f;
        } else {
            int cnt = 0;
            for (int i = 0; i < NGRID; i++) cnt += (sxs[i] <= x_pos) ? 1 : 0;
            int c1 = cnt - 1;
            if (c1 < 0) c1 = 0;
            if (c1 > NIN - 2) c1 = NIN - 2;
            s1 = c1 * NY + y; s2 = (c1 + 1) * NY + y;
            w = (sxs[c1 + 1] - x_pos) / (sxs[c1 + 1] - sxs[c1]);
        }
        g_pack[m] = make_int2(s1 | (s2 << 16), __float_as_int(w));
    }
}

// ---------------------------------------------------------------------------
// K2: table = sigmoid(H2grid @ W3 + b3)   [192 x 100] @ [100 x 1224]
// ---------------------------------------------------------------------------
#define TB_KC 50
__global__ void __launch_bounds__(256) table_gemm_kernel(const float* __restrict__ W3,
                                                         const float* __restrict__ b3) {
    __shared__ float As[64][101];
    __shared__ float Bs[TB_KC][72];

    int tid = threadIdx.x;
    int tm = tid & 31;
    int tn = tid >> 5;
    int p0 = blockIdx.x * 64;
    int n0 = blockIdx.y * 72;

    for (int idx = tid; idx < 64 * 100; idx += 256) {
        int r = idx / 100, k = idx - r * 100;
        As[r][k] = g_tabH2[(p0 + r) * KDIM + k];
    }

    float acc[2][9];
#pragma unroll
    for (int a = 0; a < 2; a++)
#pragma unroll
        for (int j = 0; j < 9; j++) acc[a][j] = 0.0f;

    for (int ch = 0; ch < 2; ch++) {
        int kb = ch * TB_KC;
        __syncthreads();
        for (int idx = tid; idx < TB_KC * 72; idx += 256) {
            int k = idx / 72, n = idx - k * 72;
            Bs[k][n] = W3[(kb + k) * NOUT + n0 + n];
        }
        __syncthreads();
#pragma unroll 5
        for (int k = 0; k < TB_KC; k++) {
            float a0 = As[tm][kb + k];
            float a1 = As[tm + 32][kb + k];
#pragma unroll
            for (int j = 0; j < 9; j++) {
                float bv = Bs[k][tn * 9 + j];
                acc[0][j] = fmaf(a0, bv, acc[0][j]);
                acc[1][j] = fmaf(a1, bv, acc[1][j]);
            }
        }
    }

#pragma unroll
    for (int j = 0; j < 9; j++) {
        int col = n0 + tn * 9 + j;
        float bias = __ldg(&b3[col]);
        g_table[(p0 + tm) * NOUT + col]      = sigmoid_fast(acc[0][j] + bias);
        g_table[(p0 + tm + 32) * NOUT + col] = sigmoid_fast(acc[1][j] + bias);
    }
}

// ---------------------------------------------------------------------------
// K3: per interval i (128 blocks): extend rows i and i+1 to 2193 cols via
// the mirror map, pack half2{v0, v1-v0}, write 4 column-shifted replicas.
// ---------------------------------------------------------------------------
__global__ void __launch_bounds__(256) extend_kernel() {
    __shared__ float x0[NOUT], x1[NOUT];
    int p = blockIdx.x;          // interval 0..127
    int tid = threadIdx.x;
    const float* r0 = g_table + (size_t)p * NOUT;
    for (int c = tid; c < NOUT; c += 256) {
        x0[c] = r0[c];
        x1[c] = r0[c + NOUT];    // row p+1
    }
    __syncthreads();

    for (int c = tid; c < OUT_STRIDE; c += 256) {
        float v0, v1;
        if (c < NOUT) {
            v0 = x0[c];
            v1 = x1[c];
        } else {
            int2 pk = g_pack[c - NOUT];
            int s1 = pk.x & 0xFFFF;
            int s2 = pk.x >> 16;
            float w = __int_as_float(pk.y);
            v0 = fmaf(w, x0[s1] - x0[s2], x0[s2]);
            v1 = fmaf(w, x1[s1] - x1[s2], x1[s2]);
        }
        __half2 h = __floats2half2_rn(v0, v1 - v0);
#pragma unroll
        for (int r = 0; r < 4; r++) {
            int cc = c - r;
            if (cc >= 0)
                g_ext[(r * NT_INT + p) * TEXT + cc] = h;
        }
    }
}

// ---------------------------------------------------------------------------
// K4: eval. One block (192 thr) per sample. Single load stream:
// 16B LDG (4 cols of half2{v0,d}) -> cvt -> fp32 FMA -> 16B evict-first STG.
// ---------------------------------------------------------------------------
__global__ void __launch_bounds__(192) eval_kernel(const float* __restrict__ x,
                                                   float* __restrict__ out) {
    int b = blockIdx.x;
    int tid = threadIdx.x;

    float xv = fminf(fmaxf(x[b], XMIN), XMAX);
    float u = (xv - XMIN) * XSCALE;
    int i = (int)u;
    if (i > NT_INT - 1) i = NT_INT - 1;
    float f = u - (float)i;

    int lead = (4 - (b & 3)) & 3;
    const __half2* rep  = g_ext + (lead * NT_INT + i) * TEXT;  // shifted replica
    const __half2* rep0 = g_ext + i * TEXT;                    // replica 0
    float* orow = out + (unsigned)b * OUT_STRIDE;

    // head (c < lead, at most 3): scalar from replica 0
    if (tid < lead) {
        float2 vd = __half22float2(__ldg(rep0 + tid));
        orow[tid] = fmaf(f, vd.y, vd.x);
    }

    // body: one aligned 16B load (4 columns) -> 4 FMA -> aligned 16B store
    int nv = (OUT_STRIDE - lead) >> 2;
    const uint4* a = (const uint4*)rep;
    float* obody = orow + lead;
#pragma unroll 3
    for (int v = tid; v < nv; v += 192) {
        uint4 r4 = __ldg(a + v);
        float2 c0 = __half22float2(*(const __half2*)&r4.x);
        float2 c1 = __half22float2(*(const __half2*)&r4.y);
        float2 c2 = __half22float2(*(const __half2*)&r4.z);
        float2 c3 = __half22float2(*(const __half2*)&r4.w);
        float4 o;
        o.x = fmaf(f, c0.y, c0.x);
        o.y = fmaf(f, c1.y, c1.x);
        o.z = fmaf(f, c2.y, c2.x);
        o.w = fmaf(f, c3.y, c3.x);
        __stcs((float4*)obody + v, o);
    }

    // tail (at most 3): scalar from replica 0
    for (int c = lead + 4 * nv + tid; c < OUT_STRIDE; c += 192) {
        float2 vd = __half22float2(__ldg(rep0 + c));
        orow[c] = fmaf(f, vd.y, vd.x);
    }
}

// ---------------------------------------------------------------------------
extern "C" void kernel_launch(void* const* d_in, const int* in_sizes, int n_in,
                              void* d_out, int out_size) {
    const float* x  = (const float*)d_in[0];
    const float* W1 = (const float*)d_in[1];
    const float* b1 = (const float*)d_in[2];
    const float* W2 = (const float*)d_in[3];
    const float* b2 = (const float*)d_in[4];
    const float* W3 = (const float*)d_in[5];
    const float* b3 = (const float*)d_in[6];
    const float* xs = (const float*)d_in[7];
    float* out = (float*)d_out;

    setup_kernel<<<TROWS + 4, 256>>>(W1, b1, W2, b2, xs);
    table_gemm_kernel<<<dim3(TROWS / 64, NOUT / 72), 256>>>(W3, b3);
    extend_kernel<<<NT_INT, 256>>>();
    eval_kernel<<<BROWS, 192>>>(x, out);
}